// round 12
// baseline (speedup 1.0000x reference)
#include <cuda_runtime.h>
#include <cuda_fp16.h>
#include <cstdint>
#include <math.h>

#define NT 1024
#define NH 1024
#define NF 4096
#define NE 8
#define NK 2
#define NSPL 2   // gemm2 split-K

// ---- device scratch ----
__device__ int    g_sel [NT*NK];
__device__ float  g_rw  [NT*NK];
__device__ int    g_slot[NT*NK];
__device__ int    g_cnt [NE];
__device__ int    g_off [NE];
__device__ int    g_tok [NT*NK];
__device__ __half g_xh[(size_t)NT*NH];
__device__ __half g_w1h[(size_t)NE*NH*NF];
__device__ __half g_w2h[(size_t)NE*NF*NH];
__device__ __half g_hh[(size_t)(NT*NK)*NF];
__device__ float  g_y[NSPL][(size_t)(NT*NK)*NH];

// ---- helpers ----
__device__ __forceinline__ uint32_t smem_u32(const void* p){
    uint32_t a; asm("{ .reg .u64 t; cvta.to.shared.u64 t, %1; cvt.u32.u64 %0, t; }":"=r"(a):"l"(p)); return a;
}
__device__ __forceinline__ void cpa16(uint32_t s, const void* g){
    asm volatile("cp.async.cg.shared.global [%0], [%1], 16;"::"r"(s),"l"(g));
}
__device__ __forceinline__ void cpa_commit(){ asm volatile("cp.async.commit_group;"); }
template<int N> __device__ __forceinline__ void cpa_wait(){ asm volatile("cp.async.wait_group %0;"::"n"(N)); }
__device__ __forceinline__ void ldmx4(uint32_t* r, uint32_t a){
    asm("ldmatrix.sync.aligned.m8n8.x4.shared.b16 {%0,%1,%2,%3}, [%4];"
        : "=r"(r[0]),"=r"(r[1]),"=r"(r[2]),"=r"(r[3]) : "r"(a) : "memory");
}
__device__ __forceinline__ void ldmx4t(uint32_t* r, uint32_t a){
    asm("ldmatrix.sync.aligned.m8n8.x4.trans.shared.b16 {%0,%1,%2,%3}, [%4];"
        : "=r"(r[0]),"=r"(r[1]),"=r"(r[2]),"=r"(r[3]) : "r"(a) : "memory");
}
__device__ __forceinline__ void mma16(float* d, const uint32_t* a, const uint32_t* b){
    asm("mma.sync.aligned.m16n8k16.row.col.f32.f16.f16.f32 "
        "{%0,%1,%2,%3}, {%4,%5,%6,%7}, {%8,%9}, {%0,%1,%2,%3};"
        : "+f"(d[0]),"+f"(d[1]),"+f"(d[2]),"+f"(d[3])
        : "r"(a[0]),"r"(a[1]),"r"(a[2]),"r"(a[3]),"r"(b[0]),"r"(b[1]));
}
__device__ __forceinline__ float gelu_exact(float v){
    return 0.5f * v * (1.0f + erff(v * 0.70710678118654752f));
}

// ---- weight conversion ----
__global__ void convert_w(const float* __restrict__ w1, const float* __restrict__ w2){
    const size_t N1 = (size_t)NE*NH*NF;
    size_t i = ((size_t)blockIdx.x*blockDim.x + threadIdx.x) * 8;
    const float* src; __half* dst;
    if (i < N1){ src = w1 + i;        dst = g_w1h + i; }
    else       { src = w2 + (i - N1); dst = g_w2h + (i - N1); }
    float4 v0 = *(const float4*)src;
    float4 v1 = *(const float4*)(src + 4);
    __half2* d2 = (__half2*)dst;
    d2[0] = __floats2half2_rn(v0.x, v0.y);
    d2[1] = __floats2half2_rn(v0.z, v0.w);
    d2[2] = __floats2half2_rn(v1.x, v1.y);
    d2[3] = __floats2half2_rn(v1.z, v1.w);
}

// ---- router ----
__global__ void router_kernel(const float* __restrict__ x,
                              const float* __restrict__ gw,
                              const float* __restrict__ gb){
    __shared__ float4 sg[NE*NH/4];
    int tid = threadIdx.x;
    for (int i = tid; i < NE*NH/4; i += blockDim.x) sg[i] = ((const float4*)gw)[i];
    __syncthreads();
    int t = blockIdx.x*blockDim.x + tid;
    const float4* xr = (const float4*)(x + (size_t)t*NH);
    __half2* xc = (__half2*)(g_xh + (size_t)t*NH);
    float acc[NE];
#pragma unroll
    for (int e=0;e<NE;e++) acc[e] = gb[e];
    for (int i=0;i<NH/4;i++){
        float4 xv = xr[i];
        xc[i*2+0] = __floats2half2_rn(xv.x, xv.y);
        xc[i*2+1] = __floats2half2_rn(xv.z, xv.w);
#pragma unroll
        for (int e=0;e<NE;e++){
            float4 g = sg[e*(NH/4)+i];
            acc[e] += xv.x*g.x + xv.y*g.y + xv.z*g.z + xv.w*g.w;
        }
    }
    int i0=0; float l0=acc[0];
#pragma unroll
    for (int e=1;e<NE;e++) if (acc[e]>l0){ l0=acc[e]; i0=e; }
    int i1=-1; float l1=-3.4e38f;
#pragma unroll
    for (int e=0;e<NE;e++) if (e!=i0 && acc[e]>l1){ l1=acc[e]; i1=e; }
    float p0 = 1.0f/(1.0f+expf(l1-l0));
    g_sel[t*2+0]=i0; g_sel[t*2+1]=i1;
    g_rw [t*2+0]=p0; g_rw [t*2+1]=1.0f-p0;
}

// ---- count + scan + scatter, one block ----
__global__ void scanfill_kernel(){
    __shared__ int scnt[NE], scur[NE];
    int tid = threadIdx.x;
    if (tid < NE){ scnt[tid] = 0; scur[tid] = 0; }
    __syncthreads();
    int e0 = g_sel[tid*2+0], e1 = g_sel[tid*2+1];
    atomicAdd(&scnt[e0],1);
    atomicAdd(&scnt[e1],1);
    __syncthreads();
    if (tid == 0){
        int o = 0;
        for (int e=0;e<NE;e++){ g_off[e]=o; g_cnt[e]=scnt[e]; o += scnt[e]; }
    }
    __syncthreads();
#pragma unroll
    for (int k=0;k<NK;k++){
        int e = g_sel[tid*2+k];
        int pos = atomicAdd(&scur[e],1);
        int idx = g_off[e]+pos;
        g_tok[idx]     = tid;
        g_slot[tid*2+k]= idx;
    }
}

// ---- grouped fp16 mma GEMM: CTA 128x64, BK=32, 256 thr = 8 warps (4m x 2n),
// warp tile 32x32, target 3 CTAs/SM (24 warps). 3-stage cp.async, 1 sync/ktile.

#define ASTR 40      // halves per A row (32 + 8 pad): 5 units/row -> conflict-free ldmx4
#define BSTR 72      // halves per B row (64 + 8 pad): 9 units/row -> conflict-free ldmx4t
#define STG_AH (128*ASTR)          // 5120 halves
#define STG_BH (32*BSTR)           // 2304 halves
#define STG_H  (STG_AH + STG_BH)   // 7424 halves
#define NSTG 3
#define SMEM_SZ (NSTG*STG_H*2)     // 44544 bytes -> 3 CTAs = 133632 B

template<int MODE>
__global__ __launch_bounds__(256, 3)
void moe_gemm(const __half* __restrict__ Asrc,
              const __half* __restrict__ W,
              const float* __restrict__ bias){
    const int z   = blockIdx.z;
    const int e   = (MODE==1) ? z : (z & 7);
    const int ks  = (MODE==1) ? 0 : (z >> 3);
    const int cnt = g_cnt[e];
    const int m0  = blockIdx.y * 128;
    if (m0 >= cnt) return;
    const int off = g_off[e];
    const int n0  = blockIdx.x * 64;
    const int ldB = (MODE==1) ? NF : NH;
    const int Kfull = (MODE==1) ? NH : NF;
    const int Kloc  = (MODE==1) ? NH : NF/NSPL;
    const int k0    = (MODE==1) ? 0  : ks * (NF/NSPL);
    const int KT    = Kloc / 32;

    extern __shared__ __half smem[];
    const uint32_t sb = smem_u32(smem);
    const int tid = threadIdx.x, wid = tid>>5, lane = tid&31;
    const int g = lane>>2, tg = lane&3;
    const int wm = wid&3, wn = wid>>2;   // 4m x 2n, warp tile 32x32

    // A cp.async: row tid>>1, halves (tid&1)*16 + j*8 (j=0..1)
    const int arow = tid>>1;
    const int acolh = (tid&1)*16;
    int mi = m0 + arow;
    int ci = (mi < cnt) ? mi : (cnt-1);
    const __half* aptr;
    if (MODE==1) aptr = Asrc + (size_t)g_tok[off+ci]*NH + acolh;
    else         aptr = Asrc + (size_t)(off+ci)*NF + k0 + acolh;

    // B cp.async: k-row tid>>3 (32 rows), halves (tid&7)*8
    const int brow = tid>>3;
    const int bcolh = (tid&7)*8;
    const __half* bptr = W + (size_t)e*Kfull*ldB + (size_t)(k0 + brow)*ldB + n0 + bcolh;

    const uint32_t adst = sb + (uint32_t)(arow*ASTR + acolh)*2u;
    const uint32_t bdst = sb + (uint32_t)(STG_AH + brow*BSTR + bcolh)*2u;

    auto load_stage = [&](int s, int kt){
        uint32_t ab = adst + (uint32_t)s*STG_H*2u;
        uint32_t bb = bdst + (uint32_t)s*STG_H*2u;
        const __half* ga  = aptr + kt*32;
        const __half* gbp = bptr + (size_t)kt*32*ldB;
        cpa16(ab,        ga);
        cpa16(ab + 16u,  ga + 8);
        cpa16(bb,        gbp);
    };

    load_stage(0,0); cpa_commit();
    load_stage(1,1); cpa_commit();

    // ldmatrix lane bases
    uint32_t a_lm[2], b_lm;
#pragma unroll
    for (int i=0;i<2;i++)
        a_lm[i] = sb + (uint32_t)((wm*32 + i*16 + (lane&15))*ASTR + (lane>>4)*8)*2u;
    b_lm = sb + (uint32_t)(STG_AH + (lane&15)*BSTR + wn*32 + (lane>>4)*8)*2u;

    float acc[2][4][4];
#pragma unroll
    for (int i=0;i<2;i++)
#pragma unroll
        for (int j=0;j<4;j++)
#pragma unroll
            for (int r=0;r<4;r++) acc[i][j][r] = 0.0f;

    for (int kt = 0; kt < KT; kt++){
        cpa_wait<1>();
        __syncthreads();
        if (kt + 2 < KT) load_stage((kt+2)%NSTG, kt+2);
        cpa_commit();

        const uint32_t stoff = (uint32_t)(kt%NSTG)*STG_H*2u;
#pragma unroll
        for (int kstep=0;kstep<2;kstep++){
            uint32_t af[2][4];
#pragma unroll
            for (int i=0;i<2;i++)
                ldmx4(af[i], a_lm[i] + stoff + (uint32_t)kstep*32u);
            uint32_t bf0[4], bf1[4];
            ldmx4t(bf0, b_lm + stoff + (uint32_t)kstep*(16u*BSTR*2u));
            ldmx4t(bf1, b_lm + stoff + (uint32_t)kstep*(16u*BSTR*2u) + 32u);
#pragma unroll
            for (int i=0;i<2;i++){
                mma16(acc[i][0], af[i], &bf0[0]);
                mma16(acc[i][1], af[i], &bf0[2]);
                mma16(acc[i][2], af[i], &bf1[0]);
                mma16(acc[i][3], af[i], &bf1[2]);
            }
        }
    }

    // ---- epilogue ----
    if (MODE == 1){
        const float* bp = bias + (size_t)e*NF + n0 + wn*32;
#pragma unroll
        for (int i=0;i<2;i++){
            int r0 = m0 + wm*32 + i*16 + g;
            int r1 = r0 + 8;
#pragma unroll
            for (int j=0;j<4;j++){
                int c = j*8 + tg*2;
                float b0 = __ldg(bp + c), b1v = __ldg(bp + c + 1);
                if (r0 < cnt){
                    __half2* o = (__half2*)(g_hh + (size_t)(off+r0)*NF + n0 + wn*32 + c);
                    *o = __floats2half2_rn(gelu_exact(acc[i][j][0] + b0),
                                           gelu_exact(acc[i][j][1] + b1v));
                }
                if (r1 < cnt){
                    __half2* o = (__half2*)(g_hh + (size_t)(off+r1)*NF + n0 + wn*32 + c);
                    *o = __floats2half2_rn(gelu_exact(acc[i][j][2] + b0),
                                           gelu_exact(acc[i][j][3] + b1v));
                }
            }
        }
    } else {
        float* Yb = g_y[ks];
#pragma unroll
        for (int i=0;i<2;i++){
            int r0 = m0 + wm*32 + i*16 + g;
            int r1 = r0 + 8;
#pragma unroll
            for (int j=0;j<4;j++){
                int c = n0 + wn*32 + j*8 + tg*2;
                if (r0 < cnt)
                    *(float2*)(Yb + (size_t)(off+r0)*NH + c) = make_float2(acc[i][j][0], acc[i][j][1]);
                if (r1 < cnt)
                    *(float2*)(Yb + (size_t)(off+r1)*NH + c) = make_float2(acc[i][j][2], acc[i][j][3]);
            }
        }
    }
}

// ---- combine ----
__global__ void combine_kernel(const float* __restrict__ b2, float* __restrict__ out){
    int idx = blockIdx.x*blockDim.x + threadIdx.x;
    int t  = idx >> 8;
    int h4 = (idx & 255) * 4;
    float4 a = make_float4(0.f,0.f,0.f,0.f);
#pragma unroll
    for (int k=0;k<2;k++){
        int e = g_sel[t*2+k];
        float w = g_rw[t*2+k];
        int sl = g_slot[t*2+k];
        float4 s = *(const float4*)&b2[(size_t)e*NH + h4];
#pragma unroll
        for (int p=0;p<NSPL;p++){
            float4 y = *(const float4*)&g_y[p][(size_t)sl*NH + h4];
            s.x += y.x; s.y += y.y; s.z += y.z; s.w += y.w;
        }
        a.x += w*s.x; a.y += w*s.y; a.z += w*s.z; a.w += w*s.w;
    }
    *(float4*)&out[(size_t)t*NH + h4] = a;
}

extern "C" void kernel_launch(void* const* d_in, const int* in_sizes, int n_in,
                              void* d_out, int out_size){
    const float* x  = (const float*)d_in[0];
    const float* gw = (const float*)d_in[1];
    const float* gb = (const float*)d_in[2];
    const float* w1 = (const float*)d_in[3];
    const float* b1 = (const float*)d_in[4];
    const float* w2 = (const float*)d_in[5];
    const float* b2 = (const float*)d_in[6];
    float* out = (float*)d_out;

    cudaFuncSetAttribute(moe_gemm<1>, cudaFuncAttributeMaxDynamicSharedMemorySize, SMEM_SZ);
    cudaFuncSetAttribute(moe_gemm<2>, cudaFuncAttributeMaxDynamicSharedMemorySize, SMEM_SZ);

    void *gxp = nullptr, *ghp = nullptr, *gw1p = nullptr, *gw2p = nullptr;
    cudaGetSymbolAddress(&gxp,  g_xh);
    cudaGetSymbolAddress(&ghp,  g_hh);
    cudaGetSymbolAddress(&gw1p, g_w1h);
    cudaGetSymbolAddress(&gw2p, g_w2h);

    router_kernel<<<NT/128, 128>>>(x, gw, gb);                     // 0
    scanfill_kernel<<<1, 1024>>>();                                // 1
    convert_w<<<(2*NE*NH*NF/8)/256, 256>>>(w1, w2);                // 2
    dim3 g1(NF/64, 8, NE);
    moe_gemm<1><<<g1, 256, SMEM_SZ>>>((const __half*)gxp, (const __half*)gw1p, b1);  // 3 <- ncu slot
    dim3 g2(NH/64, 8, NE*NSPL);
    moe_gemm<2><<<g2, 256, SMEM_SZ>>>((const __half*)ghp, (const __half*)gw2p, nullptr);  // 4
    combine_kernel<<<(NT*NH/4)/256, 256>>>(b2, out);                                      // 5
}

// round 15
// speedup vs baseline: 1.0783x; 1.0783x over previous
#include <cuda_runtime.h>
#include <cuda_fp16.h>
#include <cstdint>
#include <math.h>

#define NT 1024
#define NH 1024
#define NF 4096
#define NE 8
#define NK 2
#define NSPL 4   // gemm2 split-K

// ---- device scratch ----
__device__ int    g_sel [NT*NK];
__device__ float  g_rw  [NT*NK];
__device__ int    g_slot[NT*NK];
__device__ int    g_cnt [NE];
__device__ int    g_off [NE];
__device__ int    g_tok [NT*NK];
__device__ __half g_xh[(size_t)NT*NH];
__device__ __half g_w1h[(size_t)NE*NH*NF];
__device__ __half g_w2h[(size_t)NE*NF*NH];
__device__ __half g_hh[(size_t)(NT*NK)*NF];
__device__ float  g_y[NSPL][(size_t)(NT*NK)*NH];

// ---- helpers ----
__device__ __forceinline__ uint32_t smem_u32(const void* p){
    uint32_t a; asm("{ .reg .u64 t; cvta.to.shared.u64 t, %1; cvt.u32.u64 %0, t; }":"=r"(a):"l"(p)); return a;
}
__device__ __forceinline__ void cpa16(uint32_t s, const void* g){
    asm volatile("cp.async.cg.shared.global [%0], [%1], 16;"::"r"(s),"l"(g));
}
__device__ __forceinline__ void cpa_commit(){ asm volatile("cp.async.commit_group;"); }
template<int N> __device__ __forceinline__ void cpa_wait(){ asm volatile("cp.async.wait_group %0;"::"n"(N)); }
__device__ __forceinline__ void ldmx4(uint32_t* r, uint32_t a){
    asm("ldmatrix.sync.aligned.m8n8.x4.shared.b16 {%0,%1,%2,%3}, [%4];"
        : "=r"(r[0]),"=r"(r[1]),"=r"(r[2]),"=r"(r[3]) : "r"(a) : "memory");
}
__device__ __forceinline__ void ldmx4t(uint32_t* r, uint32_t a){
    asm("ldmatrix.sync.aligned.m8n8.x4.trans.shared.b16 {%0,%1,%2,%3}, [%4];"
        : "=r"(r[0]),"=r"(r[1]),"=r"(r[2]),"=r"(r[3]) : "r"(a) : "memory");
}
__device__ __forceinline__ void mma16(float* d, const uint32_t* a, const uint32_t* b){
    asm("mma.sync.aligned.m16n8k16.row.col.f32.f16.f16.f32 "
        "{%0,%1,%2,%3}, {%4,%5,%6,%7}, {%8,%9}, {%0,%1,%2,%3};"
        : "+f"(d[0]),"+f"(d[1]),"+f"(d[2]),"+f"(d[3])
        : "r"(a[0]),"r"(a[1]),"r"(a[2]),"r"(a[3]),"r"(b[0]),"r"(b[1]));
}
__device__ __forceinline__ float gelu_exact(float v){
    return 0.5f * v * (1.0f + erff(v * 0.70710678118654752f));
}

// ---- weight conversion ----
__global__ void convert_w(const float* __restrict__ w1, const float* __restrict__ w2){
    const size_t N1 = (size_t)NE*NH*NF;
    size_t i = ((size_t)blockIdx.x*blockDim.x + threadIdx.x) * 8;
    const float* src; __half* dst;
    if (i < N1){ src = w1 + i;        dst = g_w1h + i; }
    else       { src = w2 + (i - N1); dst = g_w2h + (i - N1); }
    float4 v0 = *(const float4*)src;
    float4 v1 = *(const float4*)(src + 4);
    __half2* d2 = (__half2*)dst;
    d2[0] = __floats2half2_rn(v0.x, v0.y);
    d2[1] = __floats2half2_rn(v0.z, v0.w);
    d2[2] = __floats2half2_rn(v1.x, v1.y);
    d2[3] = __floats2half2_rn(v1.z, v1.w);
}

// ---- router ----
__global__ void router_kernel(const float* __restrict__ x,
                              const float* __restrict__ gw,
                              const float* __restrict__ gb){
    __shared__ float4 sg[NE*NH/4];
    int tid = threadIdx.x;
    for (int i = tid; i < NE*NH/4; i += blockDim.x) sg[i] = ((const float4*)gw)[i];
    __syncthreads();
    int t = blockIdx.x*blockDim.x + tid;
    const float4* xr = (const float4*)(x + (size_t)t*NH);
    __half2* xc = (__half2*)(g_xh + (size_t)t*NH);
    float acc[NE];
#pragma unroll
    for (int e=0;e<NE;e++) acc[e] = gb[e];
    for (int i=0;i<NH/4;i++){
        float4 xv = xr[i];
        xc[i*2+0] = __floats2half2_rn(xv.x, xv.y);
        xc[i*2+1] = __floats2half2_rn(xv.z, xv.w);
#pragma unroll
        for (int e=0;e<NE;e++){
            float4 g = sg[e*(NH/4)+i];
            acc[e] += xv.x*g.x + xv.y*g.y + xv.z*g.z + xv.w*g.w;
        }
    }
    int i0=0; float l0=acc[0];
#pragma unroll
    for (int e=1;e<NE;e++) if (acc[e]>l0){ l0=acc[e]; i0=e; }
    int i1=-1; float l1=-3.4e38f;
#pragma unroll
    for (int e=0;e<NE;e++) if (e!=i0 && acc[e]>l1){ l1=acc[e]; i1=e; }
    float p0 = 1.0f/(1.0f+expf(l1-l0));
    g_sel[t*2+0]=i0; g_sel[t*2+1]=i1;
    g_rw [t*2+0]=p0; g_rw [t*2+1]=1.0f-p0;
}

// ---- count + scan + scatter ----
__global__ void scanfill_kernel(){
    __shared__ int scnt[NE], scur[NE];
    int tid = threadIdx.x;
    if (tid < NE){ scnt[tid] = 0; scur[tid] = 0; }
    __syncthreads();
    int e0 = g_sel[tid*2+0], e1 = g_sel[tid*2+1];
    atomicAdd(&scnt[e0],1);
    atomicAdd(&scnt[e1],1);
    __syncthreads();
    if (tid == 0){
        int o = 0;
        for (int e=0;e<NE;e++){ g_off[e]=o; g_cnt[e]=scnt[e]; o += scnt[e]; }
    }
    __syncthreads();
#pragma unroll
    for (int k=0;k<NK;k++){
        int e = g_sel[tid*2+k];
        int pos = atomicAdd(&scur[e],1);
        int idx = g_off[e]+pos;
        g_tok[idx]     = tid;
        g_slot[tid*2+k]= idx;
    }
}

// ---- grouped fp16 mma GEMM ----
// CTA 128x128, BK=32, 256 thr = 8 warps (4m x 2n), warp tile 32x64, 2 CTAs/SM.
// 5-stage cp.async pipeline, wait_group<3> => prefetch distance 4 ktiles.

#define ASTR 40      // halves per A row (32 + 8 pad)
#define BSTR 136     // halves per B row (128 + 8 pad)
#define STG_AH (128*ASTR)          // 5120 halves
#define STG_BH (32*BSTR)           // 4352 halves
#define STG_H  (STG_AH + STG_BH)   // 9472 halves
#define NSTG 5
#define SMEM_SZ (NSTG*STG_H*2)     // 94720 bytes -> 2 CTAs = 189440 B

template<int MODE>
__global__ __launch_bounds__(256, 2)
void moe_gemm(const __half* __restrict__ Asrc,
              const __half* __restrict__ W,
              const float* __restrict__ bias){
    const int z   = blockIdx.z;
    const int e   = (MODE==1) ? z : (z & 7);
    const int ks  = (MODE==1) ? 0 : (z >> 3);
    const int cnt = g_cnt[e];
    const int m0  = blockIdx.y * 128;
    if (m0 >= cnt) return;
    const int off = g_off[e];
    const int n0  = blockIdx.x * 128;
    const int ldB = (MODE==1) ? NF : NH;
    const int Kfull = (MODE==1) ? NH : NF;
    const int Kloc  = (MODE==1) ? NH : NF/NSPL;
    const int k0    = (MODE==1) ? 0  : ks * (NF/NSPL);
    const int KT    = Kloc / 32;

    extern __shared__ __half smem[];
    const uint32_t sb = smem_u32(smem);
    const int tid = threadIdx.x, wid = tid>>5, lane = tid&31;
    const int g = lane>>2, tg = lane&3;
    const int wm = wid&3, wn = wid>>2;   // 4m x 2n, warp tile 32x64

    // A cp.async: row tid>>1 (128), halves (tid&1)*16 + {0,8}
    const int arow = tid>>1;
    const int acolh = (tid&1)*16;
    int mi = m0 + arow;
    int ci = (mi < cnt) ? mi : (cnt-1);
    const __half* aptr;
    if (MODE==1) aptr = Asrc + (size_t)g_tok[off+ci]*NH + acolh;
    else         aptr = Asrc + (size_t)(off+ci)*NF + k0 + acolh;

    // B cp.async: k-row tid>>3 (32), halves (tid&7)*16 + {0,8}
    const int brow = tid>>3;
    const int bcolh = (tid&7)*16;
    const __half* bptr = W + (size_t)e*Kfull*ldB + (size_t)(k0 + brow)*ldB + n0 + bcolh;

    const uint32_t adst = sb + (uint32_t)(arow*ASTR + acolh)*2u;
    const uint32_t bdst = sb + (uint32_t)(STG_AH + brow*BSTR + bcolh)*2u;

    auto load_stage = [&](int s, int kt){
        uint32_t ab = adst + (uint32_t)s*STG_H*2u;
        uint32_t bb = bdst + (uint32_t)s*STG_H*2u;
        const __half* ga  = aptr + kt*32;
        const __half* gbp = bptr + (size_t)kt*32*ldB;
        cpa16(ab,       ga);
        cpa16(ab + 16u, ga + 8);
        cpa16(bb,       gbp);
        cpa16(bb + 16u, gbp + 8);
    };

#pragma unroll
    for (int s=0;s<4;s++){ load_stage(s,s); cpa_commit(); }

    // ldmatrix lane bases
    uint32_t a_lm[2], b_lm[4];
#pragma unroll
    for (int i=0;i<2;i++)
        a_lm[i] = sb + (uint32_t)((wm*32 + i*16 + (lane&15))*ASTR + (lane>>4)*8)*2u;
#pragma unroll
    for (int jj=0;jj<4;jj++)
        b_lm[jj] = sb + (uint32_t)(STG_AH + (lane&15)*BSTR + wn*64 + jj*16 + (lane>>4)*8)*2u;

    float acc[2][8][4];
#pragma unroll
    for (int i=0;i<2;i++)
#pragma unroll
        for (int j=0;j<8;j++)
#pragma unroll
            for (int r=0;r<4;r++) acc[i][j][r] = 0.0f;

    for (int kt = 0; kt < KT; kt++){
        cpa_wait<3>();           // stage kt landed (issued 4 iters ago)
        __syncthreads();
        if (kt + 4 < KT) load_stage((kt+4)%NSTG, kt+4);  // reuses slot (kt-1)%5
        cpa_commit();

        const uint32_t stoff = (uint32_t)(kt%NSTG)*STG_H*2u;
#pragma unroll
        for (int kstep=0;kstep<2;kstep++){
            uint32_t af[2][4];
#pragma unroll
            for (int i=0;i<2;i++)
                ldmx4(af[i], a_lm[i] + stoff + (uint32_t)kstep*32u);
            uint32_t bf[4][4];
#pragma unroll
            for (int jj=0;jj<4;jj++)
                ldmx4t(bf[jj], b_lm[jj] + stoff + (uint32_t)kstep*(16u*BSTR*2u));
#pragma unroll
            for (int i=0;i<2;i++)
#pragma unroll
                for (int jj=0;jj<4;jj++){
                    mma16(acc[i][jj*2+0], af[i], &bf[jj][0]);
                    mma16(acc[i][jj*2+1], af[i], &bf[jj][2]);
                }
        }
    }

    // ---- epilogue ----
    if (MODE == 1){
        const float* bp = bias + (size_t)e*NF + n0 + wn*64;
#pragma unroll
        for (int i=0;i<2;i++){
            int r0 = m0 + wm*32 + i*16 + g;
            int r1 = r0 + 8;
#pragma unroll
            for (int j=0;j<8;j++){
                int c = j*8 + tg*2;
                float b0 = __ldg(bp + c), b1v = __ldg(bp + c + 1);
                if (r0 < cnt){
                    __half2* o = (__half2*)(g_hh + (size_t)(off+r0)*NF + n0 + wn*64 + c);
                    *o = __floats2half2_rn(gelu_exact(acc[i][j][0] + b0),
                                           gelu_exact(acc[i][j][1] + b1v));
                }
                if (r1 < cnt){
                    __half2* o = (__half2*)(g_hh + (size_t)(off+r1)*NF + n0 + wn*64 + c);
                    *o = __floats2half2_rn(gelu_exact(acc[i][j][2] + b0),
                                           gelu_exact(acc[i][j][3] + b1v));
                }
            }
        }
    } else {
        float* Yb = g_y[ks];
#pragma unroll
        for (int i=0;i<2;i++){
            int r0 = m0 + wm*32 + i*16 + g;
            int r1 = r0 + 8;
#pragma unroll
            for (int j=0;j<8;j++){
                int c = n0 + wn*64 + j*8 + tg*2;
                if (r0 < cnt)
                    *(float2*)(Yb + (size_t)(off+r0)*NH + c) = make_float2(acc[i][j][0], acc[i][j][1]);
                if (r1 < cnt)
                    *(float2*)(Yb + (size_t)(off+r1)*NH + c) = make_float2(acc[i][j][2], acc[i][j][3]);
            }
        }
    }
}

// ---- combine ----
__global__ void combine_kernel(const float* __restrict__ b2, float* __restrict__ out){
    int idx = blockIdx.x*blockDim.x + threadIdx.x;
    int t  = idx >> 8;
    int h4 = (idx & 255) * 4;
    float4 a = make_float4(0.f,0.f,0.f,0.f);
#pragma unroll
    for (int k=0;k<2;k++){
        int e = g_sel[t*2+k];
        float w = g_rw[t*2+k];
        int sl = g_slot[t*2+k];
        float4 s = *(const float4*)&b2[(size_t)e*NH + h4];
#pragma unroll
        for (int p=0;p<NSPL;p++){
            float4 y = *(const float4*)&g_y[p][(size_t)sl*NH + h4];
            s.x += y.x; s.y += y.y; s.z += y.z; s.w += y.w;
        }
        a.x += w*s.x; a.y += w*s.y; a.z += w*s.z; a.w += w*s.w;
    }
    *(float4*)&out[(size_t)t*NH + h4] = a;
}

extern "C" void kernel_launch(void* const* d_in, const int* in_sizes, int n_in,
                              void* d_out, int out_size){
    const float* x  = (const float*)d_in[0];
    const float* gw = (const float*)d_in[1];
    const float* gb = (const float*)d_in[2];
    const float* w1 = (const float*)d_in[3];
    const float* b1 = (const float*)d_in[4];
    const float* w2 = (const float*)d_in[5];
    const float* b2 = (const float*)d_in[6];
    float* out = (float*)d_out;

    cudaFuncSetAttribute(moe_gemm<1>, cudaFuncAttributeMaxDynamicSharedMemorySize, SMEM_SZ);
    cudaFuncSetAttribute(moe_gemm<2>, cudaFuncAttributeMaxDynamicSharedMemorySize, SMEM_SZ);

    void *gxp = nullptr, *ghp = nullptr, *gw1p = nullptr, *gw2p = nullptr;
    cudaGetSymbolAddress(&gxp,  g_xh);
    cudaGetSymbolAddress(&ghp,  g_hh);
    cudaGetSymbolAddress(&gw1p, g_w1h);
    cudaGetSymbolAddress(&gw2p, g_w2h);

    router_kernel<<<NT/128, 128>>>(x, gw, gb);                     // 0
    scanfill_kernel<<<1, 1024>>>();                                // 1
    convert_w<<<(2*NE*NH*NF/8)/256, 256>>>(w1, w2);                // 2
    dim3 g1(NF/128, 8, NE);
    moe_gemm<1><<<g1, 256, SMEM_SZ>>>((const __half*)gxp, (const __half*)gw1p, b1);  // 3 <- ncu slot
    dim3 g2(NH/128, 8, NE*NSPL);
    moe_gemm<2><<<g2, 256, SMEM_SZ>>>((const __half*)ghp, (const __half*)gw2p, nullptr);  // 4
    combine_kernel<<<(NT*NH/4)/256, 256>>>(b2, out);                                      // 5
}